// round 3
// baseline (speedup 1.0000x reference)
#include <cuda_runtime.h>

#define B_  32
#define NJ  2048
#define IL  32
#define CC  32
#define LL  32
#define KK  1024  // CC*LL
#define JT  16    // j per gemm block

// Scratch (allocation-free rule: __device__ globals)
__device__ float g_u[(size_t)B_ * NJ * KK];   // 256 MiB, [b][j][k]
__device__ float g_b[(size_t)B_ * NJ * CC];   // routing logits
__device__ float g_s[B_ * KK];                // s accumulator
__device__ float g_v[B_ * KK];                // current v

__global__ void zero_s() { g_s[blockIdx.x * 1024 + threadIdx.x] = 0.f; }

// ---------------------------------------------------------------------------
// Kernel 1: u[b,j,k] = sum_i x[b,j,i] * W[j,i,k], fused with s0 partial sums.
// Block = (k-slice of 256, 16 j's). Thread owns 4 consecutive k and 8 b's.
// W is read exactly once; u written once; Sigma_j u accumulated in regs then
// atomically added into g_s.
// ---------------------------------------------------------------------------
__global__ void __launch_bounds__(256) gemm_u_k(const float* __restrict__ x,
                                                const float* __restrict__ W) {
    const int kt = blockIdx.x;            // 0..3
    const int j0 = blockIdx.y * JT;       // 0..2047 step 16
    const int t  = threadIdx.x;
    const int kg = t & 63;                // float4 group within slice
    const int bg = t >> 6;                // 0..3 -> b = bg*8 + bb
    const int k  = kt * 256 + kg * 4;

    __shared__ float xs[32][33];          // [b][i], pad kills STS conflicts

    float4 s_acc[8];
    #pragma unroll
    for (int bb = 0; bb < 8; ++bb) s_acc[bb] = make_float4(0.f, 0.f, 0.f, 0.f);

    for (int jj = 0; jj < JT; ++jj) {
        const int j = j0 + jj;
        __syncthreads();
        {   // stage x[b][j][:] (1024 floats) into smem, coalesced
            int lb = t >> 3, i0 = (t & 7) << 2;
            float4 xv = *(const float4*)(x + ((size_t)lb * NJ + j) * IL + i0);
            xs[lb][i0 + 0] = xv.x; xs[lb][i0 + 1] = xv.y;
            xs[lb][i0 + 2] = xv.z; xs[lb][i0 + 3] = xv.w;
        }
        __syncthreads();

        const float* Wj = W + (size_t)j * (IL * KK) + k;
        float4 acc[8];
        #pragma unroll
        for (int bb = 0; bb < 8; ++bb) acc[bb] = make_float4(0.f, 0.f, 0.f, 0.f);

        #pragma unroll 4
        for (int i = 0; i < IL; ++i) {
            float4 w4 = __ldg((const float4*)(Wj + (size_t)i * KK));
            #pragma unroll
            for (int bb = 0; bb < 8; ++bb) {
                float xv = xs[bg * 8 + bb][i];
                acc[bb].x = fmaf(xv, w4.x, acc[bb].x);
                acc[bb].y = fmaf(xv, w4.y, acc[bb].y);
                acc[bb].z = fmaf(xv, w4.z, acc[bb].z);
                acc[bb].w = fmaf(xv, w4.w, acc[bb].w);
            }
        }

        #pragma unroll
        for (int bb = 0; bb < 8; ++bb) {
            int b = bg * 8 + bb;
            *(float4*)(g_u + ((size_t)b * NJ + j) * KK + k) = acc[bb];
            s_acc[bb].x += acc[bb].x; s_acc[bb].y += acc[bb].y;
            s_acc[bb].z += acc[bb].z; s_acc[bb].w += acc[bb].w;
        }
    }

    #pragma unroll
    for (int bb = 0; bb < 8; ++bb) {
        int b = bg * 8 + bb;
        float* sp = g_s + b * KK + k;
        atomicAdd(sp + 0, s_acc[bb].x);
        atomicAdd(sp + 1, s_acc[bb].y);
        atomicAdd(sp + 2, s_acc[bb].z);
        atomicAdd(sp + 3, s_acc[bb].w);
    }
}

// ---------------------------------------------------------------------------
// Kernel 2: fused routing pass (two sub-passes over u to keep regs <= 64).
// Warp owns 16 j rows; lane holds k = 128q + 4*lane (+0..3) per q.
//   => c(q) = 4q + (lane>>3), l = 4*(lane&7)+comp
// ---------------------------------------------------------------------------
__device__ __forceinline__ float4 ldg_nc_v4(const float4* p) {
    float4 r;
    asm volatile("ld.global.nc.v4.f32 {%0,%1,%2,%3}, [%4];"
                 : "=f"(r.x), "=f"(r.y), "=f"(r.z), "=f"(r.w) : "l"(p));
    return r;
}

__global__ void __launch_bounds__(256, 4) route_pass(int read_b, int write_b) {
    int b = blockIdx.y;
    int t = threadIdx.x, w = t >> 5, lane = t & 31;
    int g = lane >> 3, sub = lane & 7;
    __shared__ float4 vs4[256];
    __shared__ float4 sred[4][256];
    vs4[t] = ((const float4*)g_v)[b * 256 + t];
    __syncthreads();

    float4 acc[8];
    #pragma unroll
    for (int q = 0; q < 8; ++q) acc[q] = make_float4(0.f, 0.f, 0.f, 0.f);

    int j0 = blockIdx.x * 128 + w * 16;
    for (int jj = 0; jj < 16; ++jj) {
        int j = j0 + jj;
        const float4* up = (const float4*)(g_u + ((size_t)b * NJ + j) * KK);

        // sub-pass A: dot(u, v) per capsule c
        float dots[8];
        #pragma unroll
        for (int q = 0; q < 8; ++q) {
            float4 r  = ldg_nc_v4(up + q * 32 + lane);
            float4 vv = vs4[q * 32 + lane];
            float d = r.x * vv.x + r.y * vv.y + r.z * vv.z + r.w * vv.w;
            d += __shfl_xor_sync(0xffffffffu, d, 1);
            d += __shfl_xor_sync(0xffffffffu, d, 2);
            d += __shfl_xor_sync(0xffffffffu, d, 4);
            dots[q] = d;   // full dot for c = 4q+g, replicated over 8 lanes
        }

        size_t bbase = ((size_t)b * NJ + j) * CC;
        if (read_b) {
            float bl = g_b[bbase + lane];
            #pragma unroll
            for (int q = 0; q < 8; ++q)
                dots[q] += __shfl_sync(0xffffffffu, bl, 4 * q + g);
        }
        if (write_b) {
            float wv = dots[0];
            #pragma unroll
            for (int q = 1; q < 8; ++q)
                if (sub == q) wv = dots[q];
            g_b[bbase + 4 * sub + g] = wv;  // bijective lane -> c map
        }

        // softmax over all 32 c
        float m = dots[0];
        #pragma unroll
        for (int q = 1; q < 8; ++q) m = fmaxf(m, dots[q]);
        m = fmaxf(m, __shfl_xor_sync(0xffffffffu, m, 8));
        m = fmaxf(m, __shfl_xor_sync(0xffffffffu, m, 16));
        float se = 0.f;
        #pragma unroll
        for (int q = 0; q < 8; ++q) { dots[q] = __expf(dots[q] - m); se += dots[q]; }
        se += __shfl_xor_sync(0xffffffffu, se, 8);
        se += __shfl_xor_sync(0xffffffffu, se, 16);
        float inv = 1.0f / se;

        // sub-pass B: s += c * u (reload u; hits L1)
        #pragma unroll
        for (int q = 0; q < 8; ++q) {
            float cp = dots[q] * inv;
            float4 r = ldg_nc_v4(up + q * 32 + lane);
            acc[q].x = fmaf(cp, r.x, acc[q].x);
            acc[q].y = fmaf(cp, r.y, acc[q].y);
            acc[q].z = fmaf(cp, r.z, acc[q].z);
            acc[q].w = fmaf(cp, r.w, acc[q].w);
        }
    }

    // tree reduce 8 -> 4 -> 2 -> 1 warps, then atomics from warp 0
    if (w >= 4) {
        #pragma unroll
        for (int q = 0; q < 8; ++q) sred[w - 4][q * 32 + lane] = acc[q];
    }
    __syncthreads();
    if (w < 4) {
        #pragma unroll
        for (int q = 0; q < 8; ++q) {
            float4 o = sred[w][q * 32 + lane];
            acc[q].x += o.x; acc[q].y += o.y; acc[q].z += o.z; acc[q].w += o.w;
        }
    }
    __syncthreads();
    if (w >= 2 && w < 4) {
        #pragma unroll
        for (int q = 0; q < 8; ++q) sred[w - 2][q * 32 + lane] = acc[q];
    }
    __syncthreads();
    if (w < 2) {
        #pragma unroll
        for (int q = 0; q < 8; ++q) {
            float4 o = sred[w][q * 32 + lane];
            acc[q].x += o.x; acc[q].y += o.y; acc[q].z += o.z; acc[q].w += o.w;
        }
    }
    __syncthreads();
    if (w == 1) {
        #pragma unroll
        for (int q = 0; q < 8; ++q) sred[0][q * 32 + lane] = acc[q];
    }
    __syncthreads();
    if (w == 0) {
        #pragma unroll
        for (int q = 0; q < 8; ++q) {
            float4 o = sred[0][q * 32 + lane];
            acc[q].x += o.x; acc[q].y += o.y; acc[q].z += o.z; acc[q].w += o.w;
            float* sp = g_s + b * KK + (q * 32 + lane) * 4;
            atomicAdd(sp + 0, acc[q].x);
            atomicAdd(sp + 1, acc[q].y);
            atomicAdd(sp + 2, acc[q].z);
            atomicAdd(sp + 3, acc[q].w);
        }
    }
}

// ---------------------------------------------------------------------------
// Kernel 3: v = squash(s*scale + bias); also re-zeroes g_s for the next pass.
// One warp per (b,c).
// ---------------------------------------------------------------------------
__global__ void finalize(const float* __restrict__ biases,
                         float* __restrict__ out, int write_out, float scale) {
    int t = threadIdx.x, w = t >> 5, lane = t & 31;
    int bc = blockIdx.x * 8 + w;
    int c = bc & 31;
    float s = g_s[bc * 32 + lane] * scale + biases[c * 32 + lane];
    g_s[bc * 32 + lane] = 0.f;          // prep next accumulation
    float p = s * s;
    #pragma unroll
    for (int off = 16; off; off >>= 1)
        p += __shfl_xor_sync(0xffffffffu, p, off);
    float n = sqrtf(p);
    float coef = p / ((1.0f + p) * (n + 1e-7f));
    float v = coef * s;
    if (write_out) out[bc * 32 + lane] = v;
    else           g_v[bc * 32 + lane] = v;
}

// ---------------------------------------------------------------------------
extern "C" void kernel_launch(void* const* d_in, const int* in_sizes, int n_in,
                              void* d_out, int out_size) {
    const float* x      = (const float*)d_in[0];  // [B,H,W,iC,iL] == [B,NJ,IL]
    const float* W      = (const float*)d_in[1];  // [NJ, IL, KK]
    const float* biases = (const float*)d_in[2];  // [CC, LL]
    float* out = (float*)d_out;                   // [B, CC, LL]

    zero_s<<<32, 1024>>>();                       // g_s undefined on first call
    gemm_u_k<<<dim3(4, 128), 256>>>(x, W);        // u + Sigma_j u into g_s
    finalize<<<128, 256>>>(biases, out, 0, 1.0f / 32.0f);  // v0 (uniform coupling)

    route_pass<<<dim3(16, B_), 256>>>(0, 1);      // b1 = dot(u,v0); c1; s1
    finalize<<<128, 256>>>(biases, out, 0, 1.0f); // v1

    route_pass<<<dim3(16, B_), 256>>>(1, 0);      // b2 = b1 + dot(u,v1); c2; s2
    finalize<<<128, 256>>>(biases, out, 1, 1.0f); // v2 -> output
}

// round 4
// speedup vs baseline: 1.5574x; 1.5574x over previous
#include <cuda_runtime.h>
#include <cuda_fp16.h>

#define B_  32
#define NJ  2048
#define IL  32
#define CC  32
#define LL  32
#define KK  1024  // CC*LL

// Scratch (allocation-free rule: __device__ globals)
__device__ __half2 g_uh[(size_t)B_ * NJ * KK / 2];  // 128 MiB, [b][j][k]
__device__ float   g_b[(size_t)B_ * NJ * CC];       // routing logits
__device__ float   g_s[B_ * KK];                    // s accumulator
__device__ float   g_v[B_ * KK];                    // current v

__global__ void zero_s() { g_s[blockIdx.x * 1024 + threadIdx.x] = 0.f; }

// ---------------------------------------------------------------------------
// Kernel 1: u[b,j,k] = sum_i x[b,j,i] * W[j,i,k] -> fp16.  One block per j.
// Thread owns 2 adjacent k (x2 outer iters), 32 b accumulators.
// x staged as float4 in smem: 1 LDS.128 per 8 FFMA.
// ---------------------------------------------------------------------------
__global__ void __launch_bounds__(256) gemm_u(const float* __restrict__ x,
                                              const float* __restrict__ W) {
    const int j = blockIdx.x;
    const int t = threadIdx.x;
    __shared__ float4 xs4[32][8];   // [b][i4]
    {
        int b = t >> 3, i4 = t & 7;
        xs4[b][i4] = *(const float4*)(x + ((size_t)b * NJ + j) * IL + i4 * 4);
    }
    __syncthreads();
    const float* Wj = W + (size_t)j * IL * KK;

    #pragma unroll 1
    for (int kk = 0; kk < 2; ++kk) {
        const int k = 2 * t + kk * 512;
        float2 acc[32];
        #pragma unroll
        for (int b = 0; b < 32; ++b) acc[b] = make_float2(0.f, 0.f);

        #pragma unroll 2
        for (int i4 = 0; i4 < 8; ++i4) {
            float2 w0 = __ldg((const float2*)(Wj + (size_t)(i4 * 4 + 0) * KK + k));
            float2 w1 = __ldg((const float2*)(Wj + (size_t)(i4 * 4 + 1) * KK + k));
            float2 w2 = __ldg((const float2*)(Wj + (size_t)(i4 * 4 + 2) * KK + k));
            float2 w3 = __ldg((const float2*)(Wj + (size_t)(i4 * 4 + 3) * KK + k));
            #pragma unroll
            for (int b = 0; b < 32; ++b) {
                float4 xv = xs4[b][i4];
                acc[b].x = fmaf(xv.x, w0.x, fmaf(xv.y, w1.x,
                           fmaf(xv.z, w2.x, fmaf(xv.w, w3.x, acc[b].x))));
                acc[b].y = fmaf(xv.x, w0.y, fmaf(xv.y, w1.y,
                           fmaf(xv.z, w2.y, fmaf(xv.w, w3.y, acc[b].y))));
            }
        }
        #pragma unroll
        for (int b = 0; b < 32; ++b)
            g_uh[(((size_t)b * NJ + j) * KK + k) >> 1] =
                __floats2half2_rn(acc[b].x, acc[b].y);
    }
}

// ---------------------------------------------------------------------------
// Kernel 2: s0 = sum_j u / 32 + bias, v0 = squash(s0).  Block per (b,c).
// (b,c) row per j = 32 halfs = 4 float4.  t&3 = f4 slot, t>>2 = j group.
// ---------------------------------------------------------------------------
__global__ void s0v0(const float* __restrict__ biases) {
    const int c = blockIdx.x, b = blockIdx.y, t = threadIdx.x;
    const int f4 = t & 3, jg = t >> 2;
    const float4* up = (const float4*)g_uh;

    float a[8];
    #pragma unroll
    for (int e = 0; e < 8; ++e) a[e] = 0.f;

    for (int j = jg; j < NJ; j += 64) {
        float4 r = up[((size_t)b * NJ + j) * (KK / 8) + c * 4 + f4];
        const __half2* h = (const __half2*)&r;
        #pragma unroll
        for (int p = 0; p < 4; ++p) {
            float2 f = __half22float2(h[p]);
            a[2 * p]     += f.x;
            a[2 * p + 1] += f.y;
        }
    }
    // reduce over jg within warp (lane bits 2..4)
    #pragma unroll
    for (int off = 16; off >= 4; off >>= 1)
        #pragma unroll
        for (int e = 0; e < 8; ++e)
            a[e] += __shfl_xor_sync(0xffffffffu, a[e], off);

    __shared__ float sred[8][4][8];
    int w = t >> 5, lane = t & 31;
    if (lane < 4) {
        #pragma unroll
        for (int e = 0; e < 8; ++e) sred[w][lane][e] = a[e];
    }
    __syncthreads();
    if (t < 4) {
        float p = 0.f;
        #pragma unroll
        for (int e = 0; e < 8; ++e) {
            float s = 0.f;
            #pragma unroll
            for (int w8 = 0; w8 < 8; ++w8) s += sred[w8][t][e];
            s = s * (1.0f / 32.0f) + biases[c * LL + t * 8 + e];
            a[e] = s;
            p += s * s;
        }
        p += __shfl_xor_sync(0xFu, p, 1);
        p += __shfl_xor_sync(0xFu, p, 2);
        float n = sqrtf(p);
        float coef = p / ((1.0f + p) * (n + 1e-7f));
        #pragma unroll
        for (int e = 0; e < 8; ++e)
            g_v[b * KK + c * LL + t * 8 + e] = coef * a[e];
    }
}

// ---------------------------------------------------------------------------
// Kernel 3: fused routing pass.  Warp owns 16 j rows.
// Lane's float4 f(q) = q*32+lane (q=0..3) covers halfs [8f, 8f+8):
//   c = q*8 + (lane>>2), in-c offset = (lane&3)*8.
// ---------------------------------------------------------------------------
__global__ void __launch_bounds__(256) route_pass(int read_b, int write_b) {
    const int b = blockIdx.y;
    const int t = threadIdx.x, w = t >> 5, lane = t & 31;
    const int g8 = lane >> 2, s4 = lane & 3;
    __shared__ float4 vs4[256];
    __shared__ float4 sred[4][256];
    vs4[t] = ((const float4*)g_v)[b * 256 + t];
    __syncthreads();

    float4 acc4[4][2];
    #pragma unroll
    for (int q = 0; q < 4; ++q) {
        acc4[q][0] = make_float4(0.f, 0.f, 0.f, 0.f);
        acc4[q][1] = make_float4(0.f, 0.f, 0.f, 0.f);
    }

    const int j0 = blockIdx.x * 128 + w * 16;
    for (int jj = 0; jj < 16; ++jj) {
        const int j = j0 + jj;
        const float4* up = (const float4*)g_uh + ((size_t)b * NJ + j) * (KK / 8);

        float4 r[4];
        #pragma unroll
        for (int q = 0; q < 4; ++q) r[q] = __ldg(up + q * 32 + lane);

        float dots[4];
        #pragma unroll
        for (int q = 0; q < 4; ++q) {
            const __half2* h = (const __half2*)&r[q];
            float2 f0 = __half22float2(h[0]), f1 = __half22float2(h[1]);
            float2 f2 = __half22float2(h[2]), f3 = __half22float2(h[3]);
            float4 v0 = vs4[(q * 32 + lane) * 2];
            float4 v1 = vs4[(q * 32 + lane) * 2 + 1];
            float d = f0.x * v0.x + f0.y * v0.y + f1.x * v0.z + f1.y * v0.w
                    + f2.x * v1.x + f2.y * v1.y + f3.x * v1.z + f3.y * v1.w;
            d += __shfl_xor_sync(0xffffffffu, d, 1);
            d += __shfl_xor_sync(0xffffffffu, d, 2);
            dots[q] = d;   // full dot for c = q*8 + g8, replicated over 4 lanes
        }

        const size_t bbase = ((size_t)b * NJ + j) * CC;
        if (read_b) {
            float bl = g_b[bbase + lane];   // lane holds b_old for c = lane
            #pragma unroll
            for (int q = 0; q < 4; ++q)
                dots[q] += __shfl_sync(0xffffffffu, bl, q * 8 + g8);
        }
        if (write_b) {
            float wv = dots[0];
            if (s4 == 1) wv = dots[1];
            if (s4 == 2) wv = dots[2];
            if (s4 == 3) wv = dots[3];
            g_b[bbase + s4 * 8 + g8] = wv;  // bijective lane -> c map
        }

        // softmax over all 32 c
        float m = fmaxf(fmaxf(dots[0], dots[1]), fmaxf(dots[2], dots[3]));
        m = fmaxf(m, __shfl_xor_sync(0xffffffffu, m, 4));
        m = fmaxf(m, __shfl_xor_sync(0xffffffffu, m, 8));
        m = fmaxf(m, __shfl_xor_sync(0xffffffffu, m, 16));
        float se = 0.f;
        #pragma unroll
        for (int q = 0; q < 4; ++q) { dots[q] = __expf(dots[q] - m); se += dots[q]; }
        se += __shfl_xor_sync(0xffffffffu, se, 4);
        se += __shfl_xor_sync(0xffffffffu, se, 8);
        se += __shfl_xor_sync(0xffffffffu, se, 16);
        const float inv = 1.0f / se;

        #pragma unroll
        for (int q = 0; q < 4; ++q) {
            float cp = dots[q] * inv;
            const __half2* h = (const __half2*)&r[q];
            float2 f0 = __half22float2(h[0]), f1 = __half22float2(h[1]);
            float2 f2 = __half22float2(h[2]), f3 = __half22float2(h[3]);
            acc4[q][0].x = fmaf(cp, f0.x, acc4[q][0].x);
            acc4[q][0].y = fmaf(cp, f0.y, acc4[q][0].y);
            acc4[q][0].z = fmaf(cp, f1.x, acc4[q][0].z);
            acc4[q][0].w = fmaf(cp, f1.y, acc4[q][0].w);
            acc4[q][1].x = fmaf(cp, f2.x, acc4[q][1].x);
            acc4[q][1].y = fmaf(cp, f2.y, acc4[q][1].y);
            acc4[q][1].z = fmaf(cp, f3.x, acc4[q][1].z);
            acc4[q][1].w = fmaf(cp, f3.y, acc4[q][1].w);
        }
    }

    // tree reduce 8 -> 4 -> 2 -> 1 warps (elementwise over full 1024-float s)
    if (w >= 4) {
        #pragma unroll
        for (int q = 0; q < 4; ++q) {
            sred[w - 4][q * 64 + lane * 2]     = acc4[q][0];
            sred[w - 4][q * 64 + lane * 2 + 1] = acc4[q][1];
        }
    }
    __syncthreads();
    if (w < 4) {
        #pragma unroll
        for (int q = 0; q < 4; ++q) {
            float4 o0 = sred[w][q * 64 + lane * 2];
            float4 o1 = sred[w][q * 64 + lane * 2 + 1];
            acc4[q][0].x += o0.x; acc4[q][0].y += o0.y;
            acc4[q][0].z += o0.z; acc4[q][0].w += o0.w;
            acc4[q][1].x += o1.x; acc4[q][1].y += o1.y;
            acc4[q][1].z += o1.z; acc4[q][1].w += o1.w;
        }
    }
    __syncthreads();
    if (w >= 2 && w < 4) {
        #pragma unroll
        for (int q = 0; q < 4; ++q) {
            sred[w - 2][q * 64 + lane * 2]     = acc4[q][0];
            sred[w - 2][q * 64 + lane * 2 + 1] = acc4[q][1];
        }
    }
    __syncthreads();
    if (w < 2) {
        #pragma unroll
        for (int q = 0; q < 4; ++q) {
            float4 o0 = sred[w][q * 64 + lane * 2];
            float4 o1 = sred[w][q * 64 + lane * 2 + 1];
            acc4[q][0].x += o0.x; acc4[q][0].y += o0.y;
            acc4[q][0].z += o0.z; acc4[q][0].w += o0.w;
            acc4[q][1].x += o1.x; acc4[q][1].y += o1.y;
            acc4[q][1].z += o1.z; acc4[q][1].w += o1.w;
        }
    }
    __syncthreads();
    if (w == 1) {
        #pragma unroll
        for (int q = 0; q < 4; ++q) {
            sred[0][q * 64 + lane * 2]     = acc4[q][0];
            sred[0][q * 64 + lane * 2 + 1] = acc4[q][1];
        }
    }
    __syncthreads();
    if (w == 0) {
        #pragma unroll
        for (int q = 0; q < 4; ++q) {
            float4 o0 = sred[0][q * 64 + lane * 2];
            float4 o1 = sred[0][q * 64 + lane * 2 + 1];
            acc4[q][0].x += o0.x; acc4[q][0].y += o0.y;
            acc4[q][0].z += o0.z; acc4[q][0].w += o0.w;
            acc4[q][1].x += o1.x; acc4[q][1].y += o1.y;
            acc4[q][1].z += o1.z; acc4[q][1].w += o1.w;
            float* sp = g_s + b * KK + (q * 32 + lane) * 8;
            atomicAdd(sp + 0, acc4[q][0].x);
            atomicAdd(sp + 1, acc4[q][0].y);
            atomicAdd(sp + 2, acc4[q][0].z);
            atomicAdd(sp + 3, acc4[q][0].w);
            atomicAdd(sp + 4, acc4[q][1].x);
            atomicAdd(sp + 5, acc4[q][1].y);
            atomicAdd(sp + 6, acc4[q][1].z);
            atomicAdd(sp + 7, acc4[q][1].w);
        }
    }
}

// ---------------------------------------------------------------------------
// Kernel 4: v = squash(s + bias); re-zeroes g_s.  One warp per (b,c).
// ---------------------------------------------------------------------------
__global__ void finalize(const float* __restrict__ biases,
                         float* __restrict__ out, int write_out) {
    int t = threadIdx.x, w = t >> 5, lane = t & 31;
    int bc = blockIdx.x * 8 + w;
    int c = bc & 31;
    float s = g_s[bc * 32 + lane] + biases[c * 32 + lane];
    g_s[bc * 32 + lane] = 0.f;          // prep next accumulation
    float p = s * s;
    #pragma unroll
    for (int off = 16; off; off >>= 1)
        p += __shfl_xor_sync(0xffffffffu, p, off);
    float n = sqrtf(p);
    float coef = p / ((1.0f + p) * (n + 1e-7f));
    float v = coef * s;
    if (write_out) out[bc * 32 + lane] = v;
    else           g_v[bc * 32 + lane] = v;
}

// ---------------------------------------------------------------------------
extern "C" void kernel_launch(void* const* d_in, const int* in_sizes, int n_in,
                              void* d_out, int out_size) {
    const float* x      = (const float*)d_in[0];  // [B,NJ,IL]
    const float* W      = (const float*)d_in[1];  // [NJ, IL, KK]
    const float* biases = (const float*)d_in[2];  // [CC, LL]
    float* out = (float*)d_out;                   // [B, CC, LL]

    zero_s<<<32, 1024>>>();
    gemm_u<<<NJ, 256>>>(x, W);                    // u (fp16)
    s0v0<<<dim3(CC, B_), 256>>>(biases);          // r=0: v0

    route_pass<<<dim3(16, B_), 256>>>(0, 1);      // b1 = dot(u,v0); c1; s1
    finalize<<<128, 256>>>(biases, out, 0);       // v1 (zeroes g_s)

    route_pass<<<dim3(16, B_), 256>>>(1, 0);      // b2 = b1 + dot(u,v1); c2; s2
    finalize<<<128, 256>>>(biases, out, 1);       // v2 -> output
}